// round 2
// baseline (speedup 1.0000x reference)
#include <cuda_runtime.h>
#include <cstdint>

// IF neuron over x[T=4, B=32, H=512, W=1024] fp32:
//   per spatial position p: v=0; for t: v+=x[t][p]; s=(v>=1)?1:0; out[t][p]=s; v-=s
// Pure streaming: 268 MB in + 268 MB out. float4-vectorized, all 4 t-plane
// loads front-batched (MLP=4) to hide DRAM latency.

static constexpr long long SPATIAL = 32LL * 512LL * 1024LL;   // 16,777,216
static constexpr long long SPATIAL4 = SPATIAL / 4;            // 4,194,304
static constexpr int THREADS = 256;

__device__ __forceinline__ float step4(float& v, float xt) {
    v += xt;
    float s = (v >= 1.0f) ? 1.0f : 0.0f;
    v -= s;
    return s;
}

__global__ __launch_bounds__(THREADS)
void if_neuron_kernel(const float4* __restrict__ x, float4* __restrict__ out) {
    long long idx = (long long)blockIdx.x * THREADS + threadIdx.x;
    if (idx >= SPATIAL4) return;

    // 4 independent 128-bit loads issued back-to-back (MLP=4)
    float4 x0 = x[idx + 0 * SPATIAL4];
    float4 x1 = x[idx + 1 * SPATIAL4];
    float4 x2 = x[idx + 2 * SPATIAL4];
    float4 x3 = x[idx + 3 * SPATIAL4];

    float4 o0, o1, o2, o3;

    // component a
    {
        float v = 0.0f;
        o0.x = step4(v, x0.x);
        o1.x = step4(v, x1.x);
        o2.x = step4(v, x2.x);
        o3.x = step4(v, x3.x);
    }
    // component b
    {
        float v = 0.0f;
        o0.y = step4(v, x0.y);
        o1.y = step4(v, x1.y);
        o2.y = step4(v, x2.y);
        o3.y = step4(v, x3.y);
    }
    // component c
    {
        float v = 0.0f;
        o0.z = step4(v, x0.z);
        o1.z = step4(v, x1.z);
        o2.z = step4(v, x2.z);
        o3.z = step4(v, x3.z);
    }
    // component d
    {
        float v = 0.0f;
        o0.w = step4(v, x0.w);
        o1.w = step4(v, x1.w);
        o2.w = step4(v, x2.w);
        o3.w = step4(v, x3.w);
    }

    out[idx + 0 * SPATIAL4] = o0;
    out[idx + 1 * SPATIAL4] = o1;
    out[idx + 2 * SPATIAL4] = o2;
    out[idx + 3 * SPATIAL4] = o3;
}

extern "C" void kernel_launch(void* const* d_in, const int* in_sizes, int n_in,
                              void* d_out, int out_size) {
    const float4* x = (const float4*)d_in[0];
    float4* out = (float4*)d_out;

    long long nblk = (SPATIAL4 + THREADS - 1) / THREADS;  // 16384
    if_neuron_kernel<<<(unsigned)nblk, THREADS>>>(x, out);
}